// round 1
// baseline (speedup 1.0000x reference)
#include <cuda_runtime.h>
#include <stdint.h>

#define NN 100000
#define EE 1600000
#define HH 128
#define GG 512
#define CC 10
#define TOT (EE + NN)
#define BNEPS 1e-5f

// ---------------- scratch (static device globals; no allocation) ----------------
__device__ int   g_is64;
__device__ int   g_src32[EE];
__device__ int   g_dst32[EE];
__device__ int   g_batch32[NN];
__device__ int   g_deg[NN];
__device__ float g_dis[NN];
__device__ int   g_rowstart[NN + 1];
__device__ int   g_fill[NN];
__device__ int   g_blocksum[128];
__device__ int   g_blockoff[128];
__device__ int   g_csr_src[TOT];
__device__ float g_csr_norm[TOT];
__device__ float g_bufA[(size_t)NN * HH];   // GEMM output (h @ W)
__device__ float g_bufB[(size_t)NN * HH];   // aggregation output (pre-BN)
__device__ float g_psum[256 * HH];
__device__ float g_psq[256 * HH];
__device__ float g_scale[3][HH];
__device__ float g_shift[3][HH];
__device__ float g_pooled[GG * HH];
__device__ int   g_counts[GG];
__device__ float g_scaleP[HH];
__device__ float g_shiftP[HH];

// ---------------- prep kernels ----------------
__global__ void k_detect(const void* ei) {
    if (threadIdx.x == 0 && blockIdx.x == 0) {
        const long long* p = (const long long*)ei;
        int ok = 1;
        for (int i = 0; i < 256; i++) {
            long long v = p[i];
            if (v < 0 || v >= NN) { ok = 0; break; }
        }
        g_is64 = ok;
    }
}

__global__ void k_cvt_edges(const void* ei) {
    int e = blockIdx.x * blockDim.x + threadIdx.x;
    if (e >= EE) return;
    if (g_is64) {
        const long long* p = (const long long*)ei;
        g_src32[e] = (int)p[e];
        g_dst32[e] = (int)p[EE + e];
    } else {
        const int* p = (const int*)ei;
        g_src32[e] = p[e];
        g_dst32[e] = p[EE + e];
    }
}

__global__ void k_cvt_batch(const void* bt) {
    int i = blockIdx.x * blockDim.x + threadIdx.x;
    if (i >= NN) return;
    if (g_is64) g_batch32[i] = (int)((const long long*)bt)[i];
    else        g_batch32[i] = ((const int*)bt)[i];
}

__global__ void k_init_deg() {
    int i = blockIdx.x * blockDim.x + threadIdx.x;
    if (i < NN) g_deg[i] = 1;   // self-loop
}

__global__ void k_count() {
    int e = blockIdx.x * blockDim.x + threadIdx.x;
    if (e < EE) atomicAdd(&g_deg[g_dst32[e]], 1);
}

__global__ void k_dis() {
    int i = blockIdx.x * blockDim.x + threadIdx.x;
    if (i < NN) g_dis[i] = rsqrtf((float)g_deg[i]);   // deg >= 1 always
}

__global__ void k_scan1() {
    __shared__ int s[1024];
    int i = blockIdx.x * 1024 + threadIdx.x;
    int v = (i < NN) ? g_deg[i] : 0;
    s[threadIdx.x] = v;
    __syncthreads();
    for (int off = 1; off < 1024; off <<= 1) {
        int t = (threadIdx.x >= off) ? s[threadIdx.x - off] : 0;
        __syncthreads();
        s[threadIdx.x] += t;
        __syncthreads();
    }
    if (i < NN) g_rowstart[i] = s[threadIdx.x];        // inclusive within chunk
    if (threadIdx.x == 1023) g_blocksum[blockIdx.x] = s[1023];
}

__global__ void k_scan2() {
    __shared__ int s[128];
    int t = threadIdx.x;
    int v = (t < 98) ? g_blocksum[t] : 0;
    s[t] = v;
    __syncthreads();
    for (int off = 1; off < 128; off <<= 1) {
        int tv = (t >= off) ? s[t - off] : 0;
        __syncthreads();
        s[t] += tv;
        __syncthreads();
    }
    g_blockoff[t] = s[t] - v;   // exclusive
}

__global__ void k_scan3() {
    int i = blockIdx.x * 1024 + threadIdx.x;
    if (i < NN) {
        g_rowstart[i] = g_rowstart[i] - g_deg[i] + g_blockoff[blockIdx.x]; // exclusive
        if (i == NN - 1) g_rowstart[NN] = TOT;
    }
}

__global__ void k_self() {
    int i = blockIdx.x * blockDim.x + threadIdx.x;
    if (i >= NN) return;
    int rs = g_rowstart[i];
    float d = g_dis[i];
    g_csr_src[rs] = i;
    g_csr_norm[rs] = d * d;
    g_fill[i] = 1;
}

__global__ void k_build() {
    int e = blockIdx.x * blockDim.x + threadIdx.x;
    if (e >= EE) return;
    int s = g_src32[e], d = g_dst32[e];
    int p = atomicAdd(&g_fill[d], 1);
    int idx = g_rowstart[d] + p;
    g_csr_src[idx] = s;
    g_csr_norm[idx] = g_dis[s] * g_dis[d];
}

// ---------------- GEMM: C[N,128] = T(A)[N,128] @ W[128,128] ----------------
// T = identity, or fused BatchNorm(scale,shift)+ReLU applied to A on load.
template <bool TR>
__device__ __forceinline__ void gemm_body(const float* __restrict__ A,
                                          const float* __restrict__ Wm,
                                          float* __restrict__ Cm,
                                          const float* __restrict__ scl,
                                          const float* __restrict__ shf) {
    __shared__ float As[128 * 36];   // row-major, stride 36 (16B aligned)
    __shared__ float Bs[32 * 128];
    __shared__ float s_sc[128], s_sh[128];
    const int tid = threadIdx.x;
    if (TR) {
        if (tid < 128) { s_sc[tid] = scl[tid]; s_sh[tid] = shf[tid]; }
        __syncthreads();
    }
    const int row0 = blockIdx.x * 128;
    const int tx = tid & 15, ty = tid >> 4;
    float acc[8][8];
#pragma unroll
    for (int i = 0; i < 8; i++)
#pragma unroll
        for (int j = 0; j < 8; j++) acc[i][j] = 0.f;

    for (int k0 = 0; k0 < 128; k0 += 32) {
#pragma unroll
        for (int i = 0; i < 4; i++) {          // A tile: 128 rows x 32 k
            int idx = tid + i * 256;           // 0..1023
            int r = idx >> 3;
            int kq = (idx & 7) << 2;
            float4 v = make_float4(0.f, 0.f, 0.f, 0.f);
            int gr = row0 + r;
            if (gr < NN) v = *(const float4*)(A + (size_t)gr * 128 + k0 + kq);
            if (TR) {
                int kk = k0 + kq;
                v.x = fmaxf(fmaf(v.x, s_sc[kk + 0], s_sh[kk + 0]), 0.f);
                v.y = fmaxf(fmaf(v.y, s_sc[kk + 1], s_sh[kk + 1]), 0.f);
                v.z = fmaxf(fmaf(v.z, s_sc[kk + 2], s_sh[kk + 2]), 0.f);
                v.w = fmaxf(fmaf(v.w, s_sc[kk + 3], s_sh[kk + 3]), 0.f);
            }
            *(float4*)(As + r * 36 + kq) = v;
        }
#pragma unroll
        for (int i = 0; i < 4; i++) {          // B tile: 32 k x 128 cols
            int idx = tid + i * 256;
            int kr = idx >> 5;
            int cq = (idx & 31) << 2;
            *(float4*)(Bs + kr * 128 + cq) =
                *(const float4*)(Wm + (size_t)(k0 + kr) * 128 + cq);
        }
        __syncthreads();
#pragma unroll
        for (int k = 0; k < 32; k++) {
            float a[8];
#pragma unroll
            for (int i = 0; i < 4; i++) {
                a[i]     = As[(ty * 4 + i) * 36 + k];
                a[4 + i] = As[(64 + ty * 4 + i) * 36 + k];
            }
            float4 b0 = *(const float4*)(Bs + k * 128 + tx * 4);
            float4 b1 = *(const float4*)(Bs + k * 128 + 64 + tx * 4);
            float b[8] = {b0.x, b0.y, b0.z, b0.w, b1.x, b1.y, b1.z, b1.w};
#pragma unroll
            for (int i = 0; i < 8; i++)
#pragma unroll
                for (int j = 0; j < 8; j++)
                    acc[i][j] = fmaf(a[i], b[j], acc[i][j]);
        }
        __syncthreads();
    }
#pragma unroll
    for (int i = 0; i < 8; i++) {
        int r = row0 + ((i < 4) ? (ty * 4 + i) : (64 + ty * 4 + i - 4));
        if (r < NN) {
            float4 c0 = {acc[i][0], acc[i][1], acc[i][2], acc[i][3]};
            float4 c1 = {acc[i][4], acc[i][5], acc[i][6], acc[i][7]};
            *(float4*)(Cm + (size_t)r * 128 + tx * 4) = c0;
            *(float4*)(Cm + (size_t)r * 128 + 64 + tx * 4) = c1;
        }
    }
}

__global__ __launch_bounds__(256) void k_gemm_x(const float* __restrict__ A,
                                                const float* __restrict__ Wm) {
    gemm_body<false>(A, Wm, g_bufA, nullptr, nullptr);
}

template <int L>
__global__ __launch_bounds__(256) void k_gemm_h(const float* __restrict__ Wm) {
    gemm_body<true>(g_bufB, Wm, g_bufA, g_scale[L], g_shift[L]);
}

// ---------------- aggregation: bufB[dst] = sum_{e in CSR(dst)} norm_e * bufA[src_e] ----------------
__global__ __launch_bounds__(256) void k_agg() {
    int gt = blockIdx.x * blockDim.x + threadIdx.x;
    int w = gt >> 5, lane = gt & 31;
    if (w >= NN) return;
    int s0 = g_rowstart[w], s1 = g_rowstart[w + 1];
    int fo = lane * 4;
    float4 acc = make_float4(0.f, 0.f, 0.f, 0.f);
    for (int j = s0; j < s1; j++) {
        int src = g_csr_src[j];
        float nm = g_csr_norm[j];
        float4 v = *(const float4*)(g_bufA + (size_t)src * 128 + fo);
        acc.x = fmaf(nm, v.x, acc.x);
        acc.y = fmaf(nm, v.y, acc.y);
        acc.z = fmaf(nm, v.z, acc.z);
        acc.w = fmaf(nm, v.w, acc.w);
    }
    *(float4*)(g_bufB + (size_t)w * 128 + fo) = acc;
}

// ---------------- BatchNorm stats over bufB (per-feature, N rows) ----------------
__global__ void k_stats1() {
    int f = threadIdx.x;          // 128
    int b = blockIdx.x;           // 256
    float s = 0.f, q = 0.f;
    for (int r = b; r < NN; r += 256) {
        float v = g_bufB[(size_t)r * 128 + f];
        s += v;
        q = fmaf(v, v, q);
    }
    g_psum[b * 128 + f] = s;
    g_psq[b * 128 + f] = q;
}

__global__ void k_stats2(const float* __restrict__ gamma,
                         const float* __restrict__ beta, int L) {
    int f = threadIdx.x;
    float s = 0.f, q = 0.f;
    for (int b = 0; b < 256; b++) { s += g_psum[b * 128 + f]; q += g_psq[b * 128 + f]; }
    float m = s / (float)NN;
    float var = fmaxf(q / (float)NN - m * m, 0.f);
    float sc = gamma[f] * rsqrtf(var + BNEPS);
    g_scale[L][f] = sc;
    g_shift[L][f] = beta[f] - m * sc;   // GCN bias cancels inside BN
}

// ---------------- pooling ----------------
__global__ void k_zero_pool() {
    int i = blockIdx.x * blockDim.x + threadIdx.x;
    if (i < GG * HH) g_pooled[i] = 0.f;
    if (i < GG) g_counts[i] = 0;
}

__global__ __launch_bounds__(256) void k_pool() {
    int gt = blockIdx.x * blockDim.x + threadIdx.x;
    int w = gt >> 5, lane = gt & 31;
    if (w >= NN) return;
    int g = g_batch32[w];
    int fo = lane * 4;
    float4 v = *(const float4*)(g_bufB + (size_t)w * 128 + fo);
    float4 sc = *(const float4*)&g_scale[2][fo];
    float4 sh = *(const float4*)&g_shift[2][fo];
    v.x = fmaxf(fmaf(v.x, sc.x, sh.x), 0.f);
    v.y = fmaxf(fmaf(v.y, sc.y, sh.y), 0.f);
    v.z = fmaxf(fmaf(v.z, sc.z, sh.z), 0.f);
    v.w = fmaxf(fmaf(v.w, sc.w, sh.w), 0.f);
    float* base = g_pooled + (size_t)g * 128 + fo;
    atomicAdd(base + 0, v.x);
    atomicAdd(base + 1, v.y);
    atomicAdd(base + 2, v.z);
    atomicAdd(base + 3, v.w);
    if (lane == 0) atomicAdd(&g_counts[g], 1);
}

__global__ void k_pool_fin() {
    int i = blockIdx.x * blockDim.x + threadIdx.x;
    if (i >= GG * HH) return;
    int g = i >> 7;
    int c = g_counts[g];
    g_pooled[i] *= 1.f / (float)(c > 0 ? c : 1);
}

// ---------------- head ----------------
__global__ void k_headstats(const float* __restrict__ gp,
                            const float* __restrict__ bep) {
    int f = threadIdx.x;
    float s = 0.f, q = 0.f;
    for (int r = 0; r < GG; r++) {
        float v = g_pooled[(size_t)r * 128 + f];
        s += v;
        q = fmaf(v, v, q);
    }
    float m = s / (float)GG;
    float var = fmaxf(q / (float)GG - m * m, 0.f);
    float sc = gp[f] * rsqrtf(var + BNEPS);
    g_scaleP[f] = sc;
    g_shiftP[f] = bep[f] - m * sc;
}

__global__ void k_head(const float* __restrict__ lw1, const float* __restrict__ lb1,
                       const float* __restrict__ lw2, const float* __restrict__ lb2,
                       float* __restrict__ out) {
    __shared__ float zn[128], y1[128], lg[CC], lse;
    int r = blockIdx.x, t = threadIdx.x;
    zn[t] = fmaf(g_pooled[(size_t)r * 128 + t], g_scaleP[t], g_shiftP[t]);
    __syncthreads();
    float a = lb1[t];
#pragma unroll 16
    for (int k = 0; k < 128; k++) a = fmaf(zn[k], lw1[(size_t)k * 128 + t], a);
    y1[t] = fmaxf(a, 0.f);
    __syncthreads();
    if (t < CC) {
        float a2 = lb2[t];
#pragma unroll 16
        for (int k = 0; k < 128; k++) a2 = fmaf(y1[k], lw2[(size_t)k * CC + t], a2);
        lg[t] = a2;
    }
    __syncthreads();
    if (t == 0) {
        float m = lg[0];
        for (int i = 1; i < CC; i++) m = fmaxf(m, lg[i]);
        float s = 0.f;
        for (int i = 0; i < CC; i++) s += expf(lg[i] - m);
        lse = m + logf(s);
    }
    __syncthreads();
    if (t < CC) out[(size_t)r * CC + t] = lg[t] - lse;
}

// ---------------- launch ----------------
extern "C" void kernel_launch(void* const* d_in, const int* in_sizes, int n_in,
                              void* d_out, int out_size) {
    const float* x   = (const float*)d_in[0];
    const void*  ei  = d_in[1];
    const void*  bt  = d_in[2];
    const float* W1  = (const float*)d_in[3];
    const float* g1  = (const float*)d_in[5];
    const float* be1 = (const float*)d_in[6];
    const float* W2  = (const float*)d_in[7];
    const float* g2  = (const float*)d_in[9];
    const float* be2 = (const float*)d_in[10];
    const float* W3  = (const float*)d_in[11];
    const float* g3  = (const float*)d_in[13];
    const float* be3 = (const float*)d_in[14];
    const float* gp  = (const float*)d_in[15];
    const float* bep = (const float*)d_in[16];
    const float* lw1 = (const float*)d_in[17];
    const float* lb1 = (const float*)d_in[18];
    const float* lw2 = (const float*)d_in[19];
    const float* lb2 = (const float*)d_in[20];
    float* out = (float*)d_out;

    const int NB  = (NN + 255) / 256;      // 391
    const int EB  = (EE + 255) / 256;      // 6250
    const int WB  = (NN * 32 + 255) / 256; // 12500
    const int GMB = (NN + 127) / 128;      // 782

    // graph prep (runs every replay; cheap relative to layers)
    k_detect<<<1, 32>>>(ei);
    k_cvt_edges<<<EB, 256>>>(ei);
    k_cvt_batch<<<NB, 256>>>(bt);
    k_init_deg<<<NB, 256>>>();
    k_count<<<EB, 256>>>();
    k_dis<<<NB, 256>>>();
    k_scan1<<<98, 1024>>>();
    k_scan2<<<1, 128>>>();
    k_scan3<<<98, 1024>>>();
    k_self<<<NB, 256>>>();
    k_build<<<EB, 256>>>();

    // layer 1
    k_gemm_x<<<GMB, 256>>>(x, W1);
    k_agg<<<WB, 256>>>();
    k_stats1<<<256, 128>>>();
    k_stats2<<<1, 128>>>(g1, be1, 0);
    // layer 2 (BN+ReLU of layer 1 fused into A load)
    k_gemm_h<0><<<GMB, 256>>>(W2);
    k_agg<<<WB, 256>>>();
    k_stats1<<<256, 128>>>();
    k_stats2<<<1, 128>>>(g2, be2, 1);
    // layer 3
    k_gemm_h<1><<<GMB, 256>>>(W3);
    k_agg<<<WB, 256>>>();
    k_stats1<<<256, 128>>>();
    k_stats2<<<1, 128>>>(g3, be3, 2);

    // pool (BN+ReLU of layer 3 fused into pooling loads)
    k_zero_pool<<<256, 256>>>();
    k_pool<<<WB, 256>>>();
    k_pool_fin<<<256, 256>>>();

    // head
    k_headstats<<<1, 128>>>(gp, bep);
    k_head<<<GG, 128>>>(lw1, lb1, lw2, lb2, out);
}